// round 8
// baseline (speedup 1.0000x reference)
#include <cuda_runtime.h>
#include <cstdint>

#define B_    4096
#define T_    1024
#define NCTA  128
#define ROWS  64      // rows per CTA (128*64 = 8192 = 2*B_)
#define RS    36      // float2 per row; RS%16=4 -> optimal 2-wavefront LDS.64

__device__ float g_hlast[8192 * 64];

__device__ __forceinline__ float tfr(float x) {   // round-to-nearest tf32
    uint32_t r; asm("cvt.rna.tf32.f32 %0, %1;" : "=r"(r) : "f"(x));
    return __uint_as_float(r);
}
__device__ __forceinline__ float tanh_a(float x) {
    float r; asm("tanh.approx.f32 %0, %1;" : "=f"(r) : "f"(x)); return r;
}
__device__ __forceinline__ float sigm(float x) { return fmaf(tanh_a(0.5f * x), 0.5f, 0.5f); }

__device__ __forceinline__ void mma8(float d[4], uint32_t a0, uint32_t a1, uint32_t a2,
                                     uint32_t a3, uint32_t b0, uint32_t b1) {
    asm volatile("mma.sync.aligned.m16n8k8.row.col.f32.tf32.tf32.f32 "
                 "{%0,%1,%2,%3}, {%4,%5,%6,%7}, {%8,%9}, {%0,%1,%2,%3};"
                 : "+f"(d[0]), "+f"(d[1]), "+f"(d[2]), "+f"(d[3])
                 : "r"(a0), "r"(a1), "r"(a2), "r"(a3), "r"(b0), "r"(b1));
}

// ============================================================================
// GRU via mma.sync tf32, weights register-resident.
// 128 CTAs x 256 threads (8 warps): rg = w&1 (rows 32rg..+31, 2 m16 blocks),
// cg = w>>1 (16 cols of each gate). Warp tile m32 x n48.
// B fragments (104 regs) loaded ONCE before the t-loop -> zero weight LDS/step.
// K-tiles 0..7 = h (K=64); kt 8 = [x0,x1,x2,1,...] folds x + b_ih+b_hh into
// r,z pre-acts (n-gate's kt-8 rows are zero -> those 2 mmas skipped).
// Ping-pong h buffers -> single __syncthreads per step. h(t) in registers.
// smem pair layout: S[row][kt][s] = {v[8kt+s], v[8kt+s+4]}  (tf32 frag layout)
// ============================================================================
__global__ __launch_bounds__(256, 1)
void gru_kernel(const float* __restrict__ x1, const float* __restrict__ x2,
                const float* __restrict__ Wih, const float* __restrict__ Whh,
                const float* __restrict__ bih, const float* __restrict__ bhh)
{
    extern __shared__ float2 sm2[];
    float2* Bs = sm2;                       // [192][RS] (staging only)
    float2* h0 = sm2 + 192 * RS;            // [64][RS]
    float2* h1 = h0 + ROWS * RS;            // [64][RS]

    const int tid = threadIdx.x;
    const int w = tid >> 5, l = tid & 31;
    const int rg = w & 1, cg = w >> 1;
    const int gid = l >> 2, tg = l & 3;

    // ---- stage B = [Whh | x-fold tile], tf32-rounded ----
    for (int i = tid; i < 192 * RS; i += 256) {
        int n = i / RS, tt = i % RS, kt = tt >> 2, s = tt & 3;
        float2 v;
        if (kt < 8) {
            v.x = tfr(Whh[n * 64 + kt * 8 + s]);
            v.y = tfr(Whh[n * 64 + kt * 8 + s + 4]);
        } else {
            v.x = 0.0f; v.y = 0.0f;
            if (n < 128)   // r,z rows only
                v.x = tfr((s < 3) ? Wih[n * 3 + s] : (bih[n] + bhh[n]));
        }
        Bs[i] = v;
    }
    // ---- zero both h buffers ----
    {
        float* hz = reinterpret_cast<float*>(h0);
        for (int i = tid; i < 2 * ROWS * RS * 2; i += 256) hz[i] = 0.0f;
    }
    __syncthreads();
    // bias "1" column in BOTH buffers (kt=8, s=3 -> {1, 0})
    if (tid < 2 * ROWS) {
        float2* hb = (tid < ROWS) ? h0 : h1;
        hb[(tid & 63) * RS + 35] = make_float2(1.0f, 0.0f);
    }

    // ---- per-thread n-gate constants ----
    float wn0[4], wn1[4], wn2[4], bnn[4], bhn[4];
#pragma unroll
    for (int u = 0; u < 4; u++) {            // u = p*2 + q
        int j = cg * 16 + (u >> 1) * 8 + tg * 2 + (u & 1);
        int nr = 128 + j;
        wn0[u] = Wih[nr * 3 + 0]; wn1[u] = Wih[nr * 3 + 1]; wn2[u] = Wih[nr * 3 + 2];
        bnn[u] = bih[nr];         bhn[u]  = bhh[nr];
    }

    // ---- x stream: threads 0..191 own one (row, component) ----
    const float* xp = nullptr;
    int xrow = 0, xc = 0;
    if (tid < 3 * ROWS) {
        xrow = tid / 3; xc = tid % 3;
        int rho = blockIdx.x * ROWS + xrow;
        xp = (rho < B_) ? (x1 + (size_t)rho * T_ * 3 + xc)
                        : (x2 + (size_t)(rho - B_) * T_ * 3 + xc);
        h0[xrow * RS + 32 + xc] = make_float2(tfr(__ldg(xp)), 0.0f);   // x(0)
        xp += 3;
    }
    __syncthreads();

    // ---- B fragments -> registers (loop-invariant) ----
    uint32_t bx[9][6], by[9][6];
#pragma unroll
    for (int kt = 0; kt < 9; kt++)
#pragma unroll
        for (int ti = 0; ti < 6; ti++) {
            if (kt == 8 && ti >= 4) { bx[kt][ti] = 0u; by[kt][ti] = 0u; continue; }
            int n = (ti >> 1) * 64 + cg * 16 + (ti & 1) * 8 + gid;
            float2 bb = Bs[n * RS + kt * 4 + tg];
            bx[kt][ti] = __float_as_uint(bb.x);
            by[kt][ti] = __float_as_uint(bb.y);
        }

    float hold[16];     // [mb][rs][u] full-precision h(t)
#pragma unroll
    for (int i = 0; i < 16; i++) hold[i] = 0.0f;

    for (int t = 0; t < T_; t++) {
        const float2* hs = (t & 1) ? h1 : h0;
        float2*       hn = (t & 1) ? h0 : h1;

        float xnext = 0.0f;
        if (tid < 3 * ROWS && t + 1 < T_) { xnext = __ldg(xp); xp += 3; }

        float acc[2][6][4];
#pragma unroll
        for (int mb = 0; mb < 2; mb++)
#pragma unroll
            for (int i = 0; i < 6; i++)
#pragma unroll
                for (int c = 0; c < 4; c++) acc[mb][i][c] = 0.0f;

        const float2* ar = hs + (rg * 32 + gid) * RS;

#pragma unroll
        for (int kt = 0; kt < 9; kt++) {
            float2 v00 = ar[kt * 4 + tg];                 // mb0, rows gid
            float2 v01 = ar[8 * RS + kt * 4 + tg];        // mb0, rows gid+8
            float2 v10 = ar[16 * RS + kt * 4 + tg];       // mb1, rows gid
            float2 v11 = ar[24 * RS + kt * 4 + tg];       // mb1, rows gid+8
            uint32_t a00 = __float_as_uint(v00.x), a01 = __float_as_uint(v01.x);
            uint32_t a02 = __float_as_uint(v00.y), a03 = __float_as_uint(v01.y);
            uint32_t a10 = __float_as_uint(v10.x), a11 = __float_as_uint(v11.x);
            uint32_t a12 = __float_as_uint(v10.y), a13 = __float_as_uint(v11.y);
            const int tmax = (kt == 8) ? 4 : 6;   // n-gate rows of kt8 are zero
#pragma unroll
            for (int ti = 0; ti < 6; ti++) {
                if (ti >= tmax) break;
                mma8(acc[0][ti], a00, a01, a02, a03, bx[kt][ti], by[kt][ti]);
                mma8(acc[1][ti], a10, a11, a12, a13, bx[kt][ti], by[kt][ti]);
            }
        }

        // ---- gate epilogue ----
        const float* hsf = reinterpret_cast<const float*>(hs);
        float*       hnf = reinterpret_cast<float*>(hn);
#pragma unroll
        for (int mb = 0; mb < 2; mb++) {
#pragma unroll
            for (int rs = 0; rs < 2; rs++) {
                int rowl = rg * 32 + mb * 16 + gid + rs * 8;
                float xs0 = hsf[rowl * (2 * RS) + 64];
                float xs1 = hsf[rowl * (2 * RS) + 66];
                float xs2 = hsf[rowl * (2 * RS) + 68];
#pragma unroll
                for (int u = 0; u < 4; u++) {
                    int p = u >> 1, q = u & 1;
                    int c = rs * 2 + q;
                    float r  = sigm(acc[mb][p][c]);          // x + both biases folded
                    float z  = sigm(acc[mb][2 + p][c]);
                    float hh = acc[mb][4 + p][c] + bhn[u];   // h-dot + b_hh (n gate)
                    float xn = fmaf(xs2, wn2[u],
                                fmaf(xs1, wn1[u],
                                 fmaf(xs0, wn0[u], bnn[u])));
                    float nn = tanh_a(fmaf(r, hh, xn));
                    int hi = (mb * 2 + rs) * 4 + u;
                    float hv = fmaf(z, hold[hi] - nn, nn);   // (1-z)n + z*h
                    hold[hi] = hv;
                    int j = cg * 16 + p * 8 + tg * 2 + q, jm = j & 7;
                    hnf[rowl * (2 * RS) + (j >> 3) * 8 + (jm & 3) * 2 + (jm >> 2)] = tfr(hv);
                }
            }
        }
        if (tid < 3 * ROWS && t + 1 < T_)
            hn[xrow * RS + 32 + xc] = make_float2(tfr(xnext), 0.0f);

        __syncthreads();   // separates this step's reads from next step's writes
    }

    // ---- final hidden states straight from registers ----
#pragma unroll
    for (int mb = 0; mb < 2; mb++)
#pragma unroll
        for (int rs = 0; rs < 2; rs++) {
            int row = blockIdx.x * ROWS + rg * 32 + mb * 16 + gid + rs * 8;
#pragma unroll
            for (int u = 0; u < 4; u++) {
                int j = cg * 16 + (u >> 1) * 8 + tg * 2 + (u & 1);
                g_hlast[(size_t)row * 64 + j] = hold[(mb * 2 + rs) * 4 + u];
            }
        }
}

// ============================================================================
// Head: out[b] = sigmoid(W2 @ relu(W1 @ |h1-h2| + b1) + b2)
// ============================================================================
__global__ void head_kernel(const float* __restrict__ W1, const float* __restrict__ b1,
                            const float* __restrict__ W2, const float* __restrict__ b2,
                            float* __restrict__ out)
{
    __shared__ float w1s[32 * 65];
    __shared__ float diffs[64];

    const int b = blockIdx.x;
    const int l = threadIdx.x;

    for (int i = l; i < 32 * 64; i += 32) {
        int m = i >> 6, k = i & 63;
        w1s[m * 65 + k] = W1[i];
    }
    diffs[l]      = fabsf(g_hlast[b * 64 + l]      - g_hlast[(B_ + b) * 64 + l]);
    diffs[32 + l] = fabsf(g_hlast[b * 64 + 32 + l] - g_hlast[(B_ + b) * 64 + 32 + l]);
    __syncwarp();

    float acc = b1[l];
#pragma unroll
    for (int k = 0; k < 64; k++) acc = fmaf(w1s[l * 65 + k], diffs[k], acc);
    acc = fmaxf(acc, 0.0f) * W2[l];

#pragma unroll
    for (int o = 16; o > 0; o >>= 1) acc += __shfl_xor_sync(0xffffffffu, acc, o);
    if (l == 0) out[b] = sigm(acc + b2[0]);
}

// ============================================================================
extern "C" void kernel_launch(void* const* d_in, const int* in_sizes, int n_in,
                              void* d_out, int out_size)
{
    (void)in_sizes; (void)n_in; (void)out_size;
    const float* x1  = (const float*)d_in[0];
    const float* x2  = (const float*)d_in[1];
    const float* Wih = (const float*)d_in[2];
    const float* Whh = (const float*)d_in[3];
    const float* bih = (const float*)d_in[4];
    const float* bhh = (const float*)d_in[5];
    const float* W1  = (const float*)d_in[6];
    const float* b1  = (const float*)d_in[7];
    const float* W2  = (const float*)d_in[8];
    const float* b2  = (const float*)d_in[9];
    float* out = (float*)d_out;

    const int dyn_smem = (192 + 2 * ROWS) * RS * (int)sizeof(float2);  // 92160 B
    cudaFuncSetAttribute(gru_kernel, cudaFuncAttributeMaxDynamicSharedMemorySize, dyn_smem);

    gru_kernel<<<NCTA, 256, dyn_smem>>>(x1, x2, Wih, Whh, bih, bhh);
    head_kernel<<<B_, 32>>>(W1, b1, W2, b2, out);
}

// round 12
// speedup vs baseline: 2.0228x; 2.0228x over previous
#include <cuda_runtime.h>
#include <cstdint>

#define B_    4096
#define T_    1024
#define NCTA  128
#define ROWS  64      // rows per CTA
#define RSB   20      // float2 per row; 20 % 16 == 4 -> conflict-free LDS.64

__device__ float g_hlast[8192 * 64];

__device__ __forceinline__ uint32_t pbf2(float lo, float hi) {  // {lo16, hi16}
    uint32_t r; asm("cvt.rn.bf16x2.f32 %0, %1, %2;" : "=r"(r) : "f"(hi), "f"(lo));
    return r;
}
__device__ __forceinline__ float tanh_a(float x) {
    float r; asm("tanh.approx.f32 %0, %1;" : "=f"(r) : "f"(x)); return r;
}
__device__ __forceinline__ float sigm(float x) { return fmaf(tanh_a(0.5f * x), 0.5f, 0.5f); }

__device__ __forceinline__ void mma16(float d[4], uint32_t a0, uint32_t a1, uint32_t a2,
                                      uint32_t a3, uint32_t b0, uint32_t b1) {
    asm volatile("mma.sync.aligned.m16n8k16.row.col.f32.bf16.bf16.f32 "
                 "{%0,%1,%2,%3}, {%4,%5,%6,%7}, {%8,%9}, {%0,%1,%2,%3};"
                 : "+f"(d[0]), "+f"(d[1]), "+f"(d[2]), "+f"(d[3])
                 : "r"(a0), "r"(a1), "r"(a2), "r"(a3), "r"(b0), "r"(b1));
}

// ============================================================================
// GRU via mma.sync bf16 (m16n8k16). 128 CTAs x 512 threads, 16 warps:
//   warp w: rg = w&3 (rows rg*16..+15), cg = w>>2 (16 cols of each gate).
// K = 80: k 0..63 = h (bf16), k 64..79 = fold tile [x0,x1,x2,1,0..] carrying
// x and b_ih+b_hh into r,z pre-acts (n-gate fold rows zero -> mmas skipped;
// its x-part is done in f32 on the fma pipe from a separate float x buffer).
// Word layout per row: float2 idx = tg*5 + kt, .x = bf16x2{k0+2tg, +1} of the
// low k8 half, .y = same for high k8 half -> one LDS.64 = full A/B k16 frag.
// Thread's 4 h-columns pack into ONE bf16x2 float2 -> single STS.64 per row.
// h-carry (hold) stays f32 in registers; only matvec inputs see bf16 rounding.
// Ping-pong h buffers -> one __syncthreads per step.
// ============================================================================
__global__ __launch_bounds__(512, 1)
void gru_kernel(const float* __restrict__ x1, const float* __restrict__ x2,
                const float* __restrict__ Wih, const float* __restrict__ Whh,
                const float* __restrict__ bih, const float* __restrict__ bhh)
{
    extern __shared__ float2 sm2[];
    float2* Bs = sm2;                        // [192][RSB]
    float2* h0 = sm2 + 192 * RSB;            // [64][RSB]
    float2* h1 = h0 + ROWS * RSB;            // [64][RSB]
    float4* xf = reinterpret_cast<float4*>(h1 + ROWS * RSB);   // [2][64]

    const int tid = threadIdx.x;
    const int w = tid >> 5, l = tid & 31;
    const int rg = w & 3, cg = w >> 2;
    const int gid = l >> 2, tg = l & 3;

    // ---- stage B = [Whh | fold], bf16-packed ----
    for (int i = tid; i < 192 * RSB; i += 512) {
        int n = i / RSB, pi = i % RSB, tgw = pi / 5, kt = pi % 5;
        float v[4];
#pragma unroll
        for (int s = 0; s < 4; s++) {
            int k = kt * 16 + (s >> 1) * 8 + 2 * tgw + (s & 1);
            float val = 0.0f;
            if (k < 64) val = Whh[n * 64 + k];
            else if (n < 128) {               // r,z fold rows only
                int ko = k - 64;
                if (ko < 3) val = Wih[n * 3 + ko];
                else if (ko == 3) val = bih[n] + bhh[n];
            }
            v[s] = val;
        }
        Bs[i] = make_float2(__uint_as_float(pbf2(v[0], v[1])),
                            __uint_as_float(pbf2(v[2], v[3])));
    }
    // ---- zero h buffers + x float buffers ----
    {
        float* hz = reinterpret_cast<float*>(h0);
        for (int i = tid; i < 2 * ROWS * RSB * 2 + 2 * ROWS * 4; i += 512) hz[i] = 0.0f;
    }
    __syncthreads();

    // ---- per-thread n-gate constants ----
    float wn0[4], wn1[4], wn2[4], bnn[4], bhn[4];
#pragma unroll
    for (int u = 0; u < 4; u++) {            // u = p*2 + q
        int j = cg * 16 + (u >> 1) * 8 + tg * 2 + (u & 1);
        int nr = 128 + j;
        wn0[u] = Wih[nr * 3 + 0]; wn1[u] = Wih[nr * 3 + 1]; wn2[u] = Wih[nr * 3 + 2];
        bnn[u] = bih[nr];         bhn[u]  = bhh[nr];
    }

    // ---- x stream: thread tid<64 owns one row entirely ----
    const float* xp = nullptr;
    if (tid < ROWS) {
        int rho = blockIdx.x * ROWS + tid;
        xp = (rho < B_) ? (x1 + (size_t)rho * T_ * 3)
                        : (x2 + (size_t)(rho - B_) * T_ * 3);
        float a = xp[0], b = xp[1], c = xp[2];  xp += 3;   // x(0)
        h0[tid * RSB + 4] = make_float2(__uint_as_float(pbf2(a, b)), 0.0f);
        h0[tid * RSB + 9] = make_float2(__uint_as_float(pbf2(c, 1.0f)), 0.0f);
        xf[tid] = make_float4(a, b, c, 0.0f);
    }

    float hold[8];       // [rs*4 + u], f32 h-carry
#pragma unroll
    for (int i = 0; i < 8; i++) hold[i] = 0.0f;

    __syncthreads();

    for (int t = 0; t < T_; t++) {
        const float2* hs  = (t & 1) ? h1 : h0;
        float2*       hn  = (t & 1) ? h0 : h1;
        const float4* xfc = xf + (t & 1) * ROWS;
        float4*       xfn = xf + ((t + 1) & 1) * ROWS;

        float xn0 = 0.0f, xn1 = 0.0f, xn2 = 0.0f;
        if (tid < ROWS && t + 1 < T_) { xn0 = xp[0]; xn1 = xp[1]; xn2 = xp[2]; xp += 3; }

        float acc[6][4];
#pragma unroll
        for (int i = 0; i < 6; i++)
#pragma unroll
            for (int c = 0; c < 4; c++) acc[i][c] = 0.0f;

        const float2* ar = hs + (rg * 16 + gid) * RSB + tg * 5;

#pragma unroll
        for (int kt = 0; kt < 5; kt++) {
            float2 lo = ar[kt];                  // row gid
            float2 hi = ar[8 * RSB + kt];        // row gid+8
            uint32_t a0 = __float_as_uint(lo.x), a1 = __float_as_uint(hi.x);
            uint32_t a2 = __float_as_uint(lo.y), a3 = __float_as_uint(hi.y);
            const int tmax = (kt == 4) ? 4 : 6;  // n-gate fold rows are zero
#pragma unroll
            for (int ti = 0; ti < 6; ti++) {
                if (ti >= tmax) break;
                int n = (ti >> 1) * 64 + cg * 16 + (ti & 1) * 8 + gid;
                float2 bb = Bs[n * RSB + tg * 5 + kt];
                mma16(acc[ti], a0, a1, a2, a3,
                      __float_as_uint(bb.x), __float_as_uint(bb.y));
            }
        }

        // ---- gate epilogue ----
#pragma unroll
        for (int rs = 0; rs < 2; rs++) {
            int rowl = rg * 16 + gid + rs * 8;
            float4 xs = xfc[rowl];
            float hv[2][2];
#pragma unroll
            for (int u = 0; u < 4; u++) {
                int p = u >> 1, q = u & 1;
                int c = rs * 2 + q;
                float r  = sigm(acc[p][c]);              // x + both biases folded
                float z  = sigm(acc[2 + p][c]);
                float hh = acc[4 + p][c] + bhn[u];       // h-dot + b_hh (n gate)
                float xn = fmaf(xs.z, wn2[u],
                            fmaf(xs.y, wn1[u],
                             fmaf(xs.x, wn0[u], bnn[u])));
                float nn = tanh_a(fmaf(r, hh, xn));
                float h2 = fmaf(z, hold[rs * 4 + u] - nn, nn);   // (1-z)n + z*h
                hold[rs * 4 + u] = h2;
                hv[p][q] = h2;
            }
            hn[rowl * RSB + tg * 5 + cg] =
                make_float2(__uint_as_float(pbf2(hv[0][0], hv[0][1])),
                            __uint_as_float(pbf2(hv[1][0], hv[1][1])));
        }
        if (tid < ROWS && t + 1 < T_) {
            hn[tid * RSB + 4] = make_float2(__uint_as_float(pbf2(xn0, xn1)), 0.0f);
            hn[tid * RSB + 9] = make_float2(__uint_as_float(pbf2(xn2, 1.0f)), 0.0f);
            xfn[tid] = make_float4(xn0, xn1, xn2, 0.0f);
        }
        __syncthreads();   // separates this step's reads from next step's writes
    }

    // ---- final hidden states from f32 registers ----
#pragma unroll
    for (int rs = 0; rs < 2; rs++) {
        int row = blockIdx.x * ROWS + rg * 16 + gid + rs * 8;
#pragma unroll
        for (int u = 0; u < 4; u++) {
            int j = cg * 16 + (u >> 1) * 8 + tg * 2 + (u & 1);
            g_hlast[(size_t)row * 64 + j] = hold[rs * 4 + u];
        }
    }
}

// ============================================================================
// Head: out[b] = sigmoid(W2 @ relu(W1 @ |h1-h2| + b1) + b2)
// ============================================================================
__global__ void head_kernel(const float* __restrict__ W1, const float* __restrict__ b1,
                            const float* __restrict__ W2, const float* __restrict__ b2,
                            float* __restrict__ out)
{
    __shared__ float w1s[32 * 65];
    __shared__ float diffs[64];

    const int b = blockIdx.x;
    const int l = threadIdx.x;

    for (int i = l; i < 32 * 64; i += 32) {
        int m = i >> 6, k = i & 63;
        w1s[m * 65 + k] = W1[i];
    }
    diffs[l]      = fabsf(g_hlast[b * 64 + l]      - g_hlast[(B_ + b) * 64 + l]);
    diffs[32 + l] = fabsf(g_hlast[b * 64 + 32 + l] - g_hlast[(B_ + b) * 64 + 32 + l]);
    __syncwarp();

    float acc = b1[l];
#pragma unroll
    for (int k = 0; k < 64; k++) acc = fmaf(w1s[l * 65 + k], diffs[k], acc);
    acc = fmaxf(acc, 0.0f) * W2[l];

#pragma unroll
    for (int o = 16; o > 0; o >>= 1) acc += __shfl_xor_sync(0xffffffffu, acc, o);
    if (l == 0) out[b] = sigm(acc + b2[0]);
}

// ============================================================================
extern "C" void kernel_launch(void* const* d_in, const int* in_sizes, int n_in,
                              void* d_out, int out_size)
{
    (void)in_sizes; (void)n_in; (void)out_size;
    const float* x1  = (const float*)d_in[0];
    const float* x2  = (const float*)d_in[1];
    const float* Wih = (const float*)d_in[2];
    const float* Whh = (const float*)d_in[3];
    const float* bih = (const float*)d_in[4];
    const float* bhh = (const float*)d_in[5];
    const float* W1  = (const float*)d_in[6];
    const float* b1  = (const float*)d_in[7];
    const float* W2  = (const float*)d_in[8];
    const float* b2  = (const float*)d_in[9];
    float* out = (float*)d_out;

    // Bs + 2 h buffers + 2 x-float buffers
    const int dyn_smem = (192 + 2 * ROWS) * RSB * (int)sizeof(float2)
                       + 2 * ROWS * (int)sizeof(float4);           // 53248 B
    cudaFuncSetAttribute(gru_kernel, cudaFuncAttributeMaxDynamicSharedMemorySize, dyn_smem);

    gru_kernel<<<NCTA, 512, dyn_smem>>>(x1, x2, Wih, Whh, bih, bhh);
    head_kernel<<<B_, 32>>>(W1, b1, W2, b2, out);
}

// round 13
// speedup vs baseline: 2.2196x; 1.0973x over previous
#include <cuda_runtime.h>
#include <cstdint>

#define B_    4096
#define T_    1024
#define NCTA  128
#define ROWS  64      // rows per CTA
#define RSB   20      // float2 per row (160 B); proven conflict-light at R8

__device__ float g_hlast[8192 * 64];

__device__ __forceinline__ uint32_t pbf2(float lo, float hi) {  // {lo16, hi16}
    uint32_t r; asm("cvt.rn.bf16x2.f32 %0, %1, %2;" : "=r"(r) : "f"(hi), "f"(lo));
    return r;
}
__device__ __forceinline__ float tanh_a(float x) {
    float r; asm("tanh.approx.f32 %0, %1;" : "=f"(r) : "f"(x)); return r;
}
__device__ __forceinline__ float sigm(float x) { return fmaf(tanh_a(0.5f * x), 0.5f, 0.5f); }

__device__ __forceinline__ void mma16(float d[4], uint32_t a0, uint32_t a1, uint32_t a2,
                                      uint32_t a3, uint32_t b0, uint32_t b1) {
    asm volatile("mma.sync.aligned.m16n8k16.row.col.f32.bf16.bf16.f32 "
                 "{%0,%1,%2,%3}, {%4,%5,%6,%7}, {%8,%9}, {%0,%1,%2,%3};"
                 : "+f"(d[0]), "+f"(d[1]), "+f"(d[2]), "+f"(d[3])
                 : "r"(a0), "r"(a1), "r"(a2), "r"(a3), "r"(b0), "r"(b1));
}

// ============================================================================
// GRU via mma.sync bf16 (m16n8k16), B register-resident at FULL occupancy.
// 128 CTAs x 512 threads, 16 warps: rg = w&1 (rows rg*32..+31, mb 0/1),
// cg = w>>1 (cols cg*8..+7 of EACH gate). Warp tile m32 x (n8 per gate).
// Per-warp B = 14 nonzero float2 frags -> 28 regs, loaded ONCE. Zero B
// crossbar traffic in the t-loop; A (h) fragments are the only per-step loads.
// K = 80: k 0..63 = h, k 64..79 = fold tile [x0,x1,x2,1,0..] carrying x and
// b_ih+b_hh into r,z pre-acts (n-gate fold rows zero -> 2 mmas skipped; its
// x-part is f32 on the fma pipe). Thread owns cols j,j+1 (j = cg*8+2tg) for
// all 3 gates -> shuffle-free epilogue, single st.shared.b32 per row-store.
// f32 h-carry in registers; ping-pong h buffers; one __syncthreads per step.
// Word layout per row: float2 idx = tg*5 + kt; .x = bf16x2{kt*16+2tg, +1},
// .y = bf16x2{kt*16+8+2tg, +1}   (float index = row*40 + tg*10 + cg).
// ============================================================================
__global__ __launch_bounds__(512, 1)
void gru_kernel(const float* __restrict__ x1, const float* __restrict__ x2,
                const float* __restrict__ Wih, const float* __restrict__ Whh,
                const float* __restrict__ bih, const float* __restrict__ bhh)
{
    extern __shared__ float2 sm2[];
    float2* Bs = sm2;                        // [192][RSB] staging
    float2* h0 = sm2 + 192 * RSB;            // [64][RSB]
    float2* h1 = h0 + ROWS * RSB;            // [64][RSB]
    float4* xf = reinterpret_cast<float4*>(h1 + ROWS * RSB);   // [2][64]

    const int tid = threadIdx.x;
    const int w = tid >> 5, l = tid & 31;
    const int rg = w & 1, cg = w >> 1;
    const int gid = l >> 2, tg = l & 3;

    // ---- stage B = [Whh | fold], bf16-packed ----
    for (int i = tid; i < 192 * RSB; i += 512) {
        int n = i / RSB, pi = i % RSB, tgw = pi / 5, kt = pi % 5;
        float v[4];
#pragma unroll
        for (int s = 0; s < 4; s++) {
            int k = kt * 16 + (s >> 1) * 8 + 2 * tgw + (s & 1);
            float val = 0.0f;
            if (k < 64) val = Whh[n * 64 + k];
            else if (n < 128) {               // r,z fold rows only
                int ko = k - 64;
                if (ko < 3) val = Wih[n * 3 + ko];
                else if (ko == 3) val = bih[n] + bhh[n];
            }
            v[s] = val;
        }
        Bs[i] = make_float2(__uint_as_float(pbf2(v[0], v[1])),
                            __uint_as_float(pbf2(v[2], v[3])));
    }
    // ---- zero h buffers + x float buffers ----
    {
        float* hz = reinterpret_cast<float*>(h0);
        for (int i = tid; i < 2 * ROWS * RSB * 2 + 2 * ROWS * 4; i += 512) hz[i] = 0.0f;
    }
    __syncthreads();

    // ---- per-thread n-gate constants for cols j0 = cg*8+2tg, j1 = j0+1 ----
    float wn0[2], wn1[2], wn2[2], bnn[2], bhn[2];
#pragma unroll
    for (int q = 0; q < 2; q++) {
        int nr = 128 + cg * 8 + 2 * tg + q;
        wn0[q] = Wih[nr * 3 + 0]; wn1[q] = Wih[nr * 3 + 1]; wn2[q] = Wih[nr * 3 + 2];
        bnn[q] = bih[nr];         bhn[q]  = bhh[nr];
    }

    // ---- x stream: thread tid<64 owns one row ----
    const float* xp = nullptr;
    if (tid < ROWS) {
        int rho = blockIdx.x * ROWS + tid;
        xp = (rho < B_) ? (x1 + (size_t)rho * T_ * 3)
                        : (x2 + (size_t)(rho - B_) * T_ * 3);
        float a = xp[0], b = xp[1], c = xp[2];  xp += 3;   // x(0)
        h0[tid * RSB + 4] = make_float2(__uint_as_float(pbf2(a, b)), 0.0f);
        h0[tid * RSB + 9] = make_float2(__uint_as_float(pbf2(c, 1.0f)), 0.0f);
        xf[tid] = make_float4(a, b, c, 0.0f);
    }
    __syncthreads();

    // ---- B fragments -> registers (loop-invariant, 28 live regs) ----
    uint32_t bfx[5][3], bfy[5][3];
#pragma unroll
    for (int kt = 0; kt < 5; kt++)
#pragma unroll
        for (int g = 0; g < 3; g++) {
            if (kt == 4 && g == 2) { bfx[kt][g] = 0u; bfy[kt][g] = 0u; continue; }
            int n = g * 64 + cg * 8 + gid;
            float2 bb = Bs[n * RSB + tg * 5 + kt];
            bfx[kt][g] = __float_as_uint(bb.x);
            bfy[kt][g] = __float_as_uint(bb.y);
        }

    float hold[8];       // [mb*4 + rs*2 + q], f32 h-carry
#pragma unroll
    for (int i = 0; i < 8; i++) hold[i] = 0.0f;

    for (int t = 0; t < T_; t++) {
        const float2* hs  = (t & 1) ? h1 : h0;
        float2*       hn  = (t & 1) ? h0 : h1;
        const float4* xfc = xf + (t & 1) * ROWS;
        float4*       xfn = xf + ((t + 1) & 1) * ROWS;

        float xn0 = 0.0f, xn1 = 0.0f, xn2 = 0.0f;
        if (tid < ROWS && t + 1 < T_) { xn0 = xp[0]; xn1 = xp[1]; xn2 = xp[2]; xp += 3; }

        float acc[2][3][4];
#pragma unroll
        for (int mb = 0; mb < 2; mb++)
#pragma unroll
            for (int g = 0; g < 3; g++)
#pragma unroll
                for (int c = 0; c < 4; c++) acc[mb][g][c] = 0.0f;

        const float2* ar = hs + (rg * 32 + gid) * RSB + tg * 5;

#pragma unroll
        for (int kt = 0; kt < 5; kt++) {
            float2 lo0 = ar[kt];                   // mb0 rows gid
            float2 hi0 = ar[8 * RSB + kt];         // mb0 rows gid+8
            float2 lo1 = ar[16 * RSB + kt];        // mb1 rows gid
            float2 hi1 = ar[24 * RSB + kt];        // mb1 rows gid+8
            uint32_t a00 = __float_as_uint(lo0.x), a01 = __float_as_uint(hi0.x);
            uint32_t a02 = __float_as_uint(lo0.y), a03 = __float_as_uint(hi0.y);
            uint32_t a10 = __float_as_uint(lo1.x), a11 = __float_as_uint(hi1.x);
            uint32_t a12 = __float_as_uint(lo1.y), a13 = __float_as_uint(hi1.y);
            const int gmax = (kt == 4) ? 2 : 3;    // n-gate fold rows are zero
#pragma unroll
            for (int g = 0; g < 3; g++) {
                if (g >= gmax) break;
                mma16(acc[0][g], a00, a01, a02, a03, bfx[kt][g], bfy[kt][g]);
                mma16(acc[1][g], a10, a11, a12, a13, bfx[kt][g], bfy[kt][g]);
            }
        }

        // ---- gate epilogue (all 3 gates of cols j0,j1 on this thread) ----
        float* hnf = reinterpret_cast<float*>(hn);
#pragma unroll
        for (int mb = 0; mb < 2; mb++) {
#pragma unroll
            for (int rs = 0; rs < 2; rs++) {
                int rowl = rg * 32 + mb * 16 + rs * 8 + gid;
                float4 xs = xfc[rowl];
                float hq[2];
#pragma unroll
                for (int q = 0; q < 2; q++) {
                    int c = rs * 2 + q;
                    float r  = sigm(acc[mb][0][c]);          // x + both biases folded
                    float z  = sigm(acc[mb][1][c]);
                    float hh = acc[mb][2][c] + bhn[q];       // h-dot + b_hh (n gate)
                    float xn = fmaf(xs.z, wn2[q],
                                fmaf(xs.y, wn1[q],
                                 fmaf(xs.x, wn0[q], bnn[q])));
                    float nn = tanh_a(fmaf(r, hh, xn));
                    int hi = mb * 4 + rs * 2 + q;
                    float h2 = fmaf(z, hold[hi] - nn, nn);   // (1-z)n + z*h
                    hold[hi] = h2;
                    hq[q] = h2;
                }
                hnf[rowl * (2 * RSB) + tg * 10 + cg] =
                    __uint_as_float(pbf2(hq[0], hq[1]));
            }
        }
        if (tid < ROWS && t + 1 < T_) {
            hn[tid * RSB + 4] = make_float2(__uint_as_float(pbf2(xn0, xn1)), 0.0f);
            hn[tid * RSB + 9] = make_float2(__uint_as_float(pbf2(xn2, 1.0f)), 0.0f);
            xfn[tid] = make_float4(xn0, xn1, xn2, 0.0f);
        }
        __syncthreads();   // separates this step's reads from next step's writes
    }

    // ---- final hidden states from f32 registers ----
#pragma unroll
    for (int mb = 0; mb < 2; mb++)
#pragma unroll
        for (int rs = 0; rs < 2; rs++) {
            int row = blockIdx.x * ROWS + rg * 32 + mb * 16 + rs * 8 + gid;
#pragma unroll
            for (int q = 0; q < 2; q++)
                g_hlast[(size_t)row * 64 + cg * 8 + 2 * tg + q] = hold[mb * 4 + rs * 2 + q];
        }
}

// ============================================================================
// Head: out[b] = sigmoid(W2 @ relu(W1 @ |h1-h2| + b1) + b2)
// ============================================================================
__global__ void head_kernel(const float* __restrict__ W1, const float* __restrict__ b1,
                            const float* __restrict__ W2, const float* __restrict__ b2,
                            float* __restrict__ out)
{
    __shared__ float w1s[32 * 65];
    __shared__ float diffs[64];

    const int b = blockIdx.x;
    const int l = threadIdx.x;

    for (int i = l; i < 32 * 64; i += 32) {
        int m = i >> 6, k = i & 63;
        w1s[m * 65 + k] = W1[i];
    }
    diffs[l]      = fabsf(g_hlast[b * 64 + l]      - g_hlast[(B_ + b) * 64 + l]);
    diffs[32 + l] = fabsf(g_hlast[b * 64 + 32 + l] - g_hlast[(B_ + b) * 64 + 32 + l]);
    __syncwarp();

    float acc = b1[l];
#pragma unroll
    for (int k = 0; k < 64; k++) acc = fmaf(w1s[l * 65 + k], diffs[k], acc);
    acc = fmaxf(acc, 0.0f) * W2[l];

#pragma unroll
    for (int o = 16; o > 0; o >>= 1) acc += __shfl_xor_sync(0xffffffffu, acc, o);
    if (l == 0) out[b] = sigm(acc + b2[0]);
}

// ============================================================================
extern "C" void kernel_launch(void* const* d_in, const int* in_sizes, int n_in,
                              void* d_out, int out_size)
{
    (void)in_sizes; (void)n_in; (void)out_size;
    const float* x1  = (const float*)d_in[0];
    const float* x2  = (const float*)d_in[1];
    const float* Wih = (const float*)d_in[2];
    const float* Whh = (const float*)d_in[3];
    const float* bih = (const float*)d_in[4];
    const float* bhh = (const float*)d_in[5];
    const float* W1  = (const float*)d_in[6];
    const float* b1  = (const float*)d_in[7];
    const float* W2  = (const float*)d_in[8];
    const float* b2  = (const float*)d_in[9];
    float* out = (float*)d_out;

    const int dyn_smem = (192 + 2 * ROWS) * RSB * (int)sizeof(float2)
                       + 2 * ROWS * (int)sizeof(float4);           // 53248 B
    cudaFuncSetAttribute(gru_kernel, cudaFuncAttributeMaxDynamicSharedMemorySize, dyn_smem);

    gru_kernel<<<NCTA, 512, dyn_smem>>>(x1, x2, Wih, Whh, bih, bhh);
    head_kernel<<<B_, 32>>>(W1, b1, W2, b2, out);
}